// round 10
// baseline (speedup 1.0000x reference)
#include <cuda_runtime.h>
#include <cuda_bf16.h>
#include <math.h>

// Problem constants
#define VOCAB 50000
#define DIM   512
#define SEQL  512
#define BATCH 256
#define NCLS  20

// smem layout: [bar0 u64][bar1 u64] then wt[64][516], hs[16][516]
#define CSTR  516
#define RNN_SMEM_FLOATS (4 + (64 + 16) * CSTR)
#define RNN_SMEM_BYTES  (RNN_SMEM_FLOATS * 4)   // 165,136 B
#define RNN_THREADS 128
#define CLUSTER_CTAS 8

typedef unsigned long long ull;

// ---------------- device scratch (no runtime alloc allowed) ----------------
__device__ float g_embW[(size_t)VOCAB * DIM];       // emb @ Wx + b, ~100 MB
__device__ float g_h[2 * BATCH * DIM];              // ping-pong hidden state

// ---------------- cluster mbarrier helpers ----------------------------------
__device__ __forceinline__ unsigned smem_u32(const void* p) {
    unsigned a;
    asm("{ .reg .u64 t; cvta.to.shared.u64 t, %1; cvt.u32.u64 %0, t; }"
        : "=r"(a) : "l"(p));
    return a;
}
__device__ __forceinline__ void mbar_init(unsigned addr, unsigned cnt) {
    asm volatile("mbarrier.init.shared.b64 [%0], %1;" :: "r"(addr), "r"(cnt) : "memory");
}
__device__ __forceinline__ void mbar_inval(unsigned addr) {
    asm volatile("mbarrier.inval.shared.b64 [%0];" :: "r"(addr) : "memory");
}
// arrive with release at CLUSTER scope on a peer CTA's barrier (same smem offset)
__device__ __forceinline__ void mbar_arrive_cluster(unsigned local_addr, unsigned rank) {
    asm volatile(
        "{\n\t.reg .b32 ra;\n\t"
        "mapa.shared::cluster.u32 ra, %0, %1;\n\t"
        "mbarrier.arrive.release.cluster.shared::cluster.b64 _, [ra];\n\t}"
        :: "r"(local_addr), "r"(rank) : "memory");
}
// parity wait with acquire at CLUSTER scope (covers peers' global h stores)
__device__ __forceinline__ void mbar_wait_cluster(unsigned addr, unsigned parity) {
    unsigned done;
    do {
        asm volatile(
            "{\n\t.reg .pred p;\n\t"
            "mbarrier.try_wait.parity.acquire.cluster.shared::cta.b64 p, [%1], %2;\n\t"
            "selp.b32 %0, 1, 0, p;\n\t}"
            : "=r"(done) : "r"(addr), "r"(parity) : "memory");
    } while (!done);
}
__device__ __forceinline__ void cluster_sync_all() {
    asm volatile("barrier.cluster.arrive.aligned;" ::: "memory");
    asm volatile("barrier.cluster.wait.aligned;" ::: "memory");
}

// packed fp32x2 math (sm_103a native; ptxas never auto-generates these)
__device__ __forceinline__ ull fma2(ull a, ull b, ull c) {
    ull d;
    asm("fma.rn.f32x2 %0, %1, %2, %3;" : "=l"(d) : "l"(a), "l"(b), "l"(c));
    return d;
}
__device__ __forceinline__ ull add2(ull a, ull b) {
    ull d;
    asm("add.rn.f32x2 %0, %1, %2;" : "=l"(d) : "l"(a), "l"(b));
    return d;
}
__device__ __forceinline__ ull shflx64(ull v, int m) {
    unsigned lo = (unsigned)v, hi = (unsigned)(v >> 32);
    lo = __shfl_xor_sync(0xffffffffu, lo, m);
    hi = __shfl_xor_sync(0xffffffffu, hi, m);
    return ((ull)hi << 32) | (ull)lo;
}

// ---------------- kernel 1: embW = emb @ Wx + b  (fp32 tiled GEMM) ----------
// BM=128, BN=128, BK=16, 256 threads, 8x8 per thread.
__global__ __launch_bounds__(256) void embw_gemm(
    const float* __restrict__ A,    // emb [M][512]
    const float* __restrict__ B,    // Wx  [512][512]
    const float* __restrict__ bias, // b [512]
    int M)
{
    __shared__ float As[16][132];   // transposed A tile [k][m], padded
    __shared__ float Bs[16][128];   // [k][n]

    const int tid  = threadIdx.x;
    const int row0 = blockIdx.y * 128;
    const int col0 = blockIdx.x * 128;
    const int tm = tid >> 4;        // 0..15 -> 8 rows each
    const int tn = tid & 15;        // 0..15 -> cols tn*4 and 64+tn*4

    float4 acc0[8], acc1[8];
    #pragma unroll
    for (int i = 0; i < 8; i++) {
        acc0[i] = make_float4(0.f, 0.f, 0.f, 0.f);
        acc1[i] = make_float4(0.f, 0.f, 0.f, 0.f);
    }

    for (int k0 = 0; k0 < DIM; k0 += 16) {
        #pragma unroll
        for (int t = 0; t < 2; t++) {
            int idx = tid + t * 256;
            int am  = idx >> 2;
            int ak4 = (idx & 3) << 2;
            float4 av = make_float4(0.f, 0.f, 0.f, 0.f);
            if (row0 + am < M)
                av = *(const float4*)(A + (size_t)(row0 + am) * DIM + k0 + ak4);
            As[ak4 + 0][am] = av.x;
            As[ak4 + 1][am] = av.y;
            As[ak4 + 2][am] = av.z;
            As[ak4 + 3][am] = av.w;
        }
        #pragma unroll
        for (int t = 0; t < 2; t++) {
            int idx = tid + t * 256;
            int bk  = idx >> 5;
            int bn4 = (idx & 31) << 2;
            *(float4*)&Bs[bk][bn4] =
                *(const float4*)(B + (size_t)(k0 + bk) * DIM + col0 + bn4);
        }
        __syncthreads();

        #pragma unroll
        for (int kk = 0; kk < 16; kk++) {
            float4 b0 = *(const float4*)&Bs[kk][tn << 2];
            float4 b1 = *(const float4*)&Bs[kk][64 + (tn << 2)];
            float4 a0 = *(const float4*)&As[kk][tm * 8];
            float4 a1 = *(const float4*)&As[kk][tm * 8 + 4];
            float av[8] = {a0.x, a0.y, a0.z, a0.w, a1.x, a1.y, a1.z, a1.w};
            #pragma unroll
            for (int i = 0; i < 8; i++) {
                acc0[i].x += av[i] * b0.x; acc0[i].y += av[i] * b0.y;
                acc0[i].z += av[i] * b0.z; acc0[i].w += av[i] * b0.w;
                acc1[i].x += av[i] * b1.x; acc1[i].y += av[i] * b1.y;
                acc1[i].z += av[i] * b1.z; acc1[i].w += av[i] * b1.w;
            }
        }
        __syncthreads();
    }

    float4 bb0 = *(const float4*)(bias + col0 + (tn << 2));
    float4 bb1 = *(const float4*)(bias + col0 + 64 + (tn << 2));
    #pragma unroll
    for (int i = 0; i < 8; i++) {
        int row = row0 + tm * 8 + i;
        if (row < M) {
            float4 o0, o1;
            o0.x = acc0[i].x + bb0.x; o0.y = acc0[i].y + bb0.y;
            o0.z = acc0[i].z + bb0.z; o0.w = acc0[i].w + bb0.w;
            o1.x = acc1[i].x + bb1.x; o1.y = acc1[i].y + bb1.y;
            o1.z = acc1[i].z + bb1.z; o1.w = acc1[i].w + bb1.w;
            *(float4*)(g_embW + (size_t)row * DIM + col0 + (tn << 2))      = o0;
            *(float4*)(g_embW + (size_t)row * DIM + col0 + 64 + (tn << 2)) = o1;
        }
    }
}

// ---------------- kernel 2: persistent RNN recurrence -----------------------
// 128 CTAs in 16 clusters of 8 (one cluster = one row group of 16 batch rows;
// cluster rank = cg = 64-col slice).  R7 math engine verbatim; step sync via
// hardware cluster mbarriers (2 per CTA, alternating by step parity).
__global__ __launch_bounds__(RNN_THREADS, 1) __cluster_dims__(CLUSTER_CTAS, 1, 1)
void rnn_recur(
    const int*   __restrict__ x,    // [256][512] tokens
    const float* __restrict__ Wh)   // [512][512]
{
    extern __shared__ float smem[];
    ull*   bars = (ull*)smem;         // bar[0], bar[1]
    float* wt = smem + 4;             // [64][CSTR] rotated transpose
    float* hs = smem + 4 + 64 * CSTR; // [16][CSTR]

    const int tid  = threadIdx.x;
    const int warp = tid >> 5;
    const int lane = tid & 31;
    const int rg   = blockIdx.x >> 3;
    const int cg   = blockIdx.x & 7;
    const int col0 = cg * 64;
    const int row0 = rg * 16;

    const unsigned bar0 = smem_u32(&bars[0]);
    const unsigned bar1 = smem_u32(&bars[1]);

    if (tid == 0) {
        mbar_init(bar0, CLUSTER_CTAS);
        mbar_init(bar1, CLUSTER_CTAS);
    }

    // one-time rotated transposed load:
    // wt[c][ ((d>>2 + 2*(c>>3)) & 127)*4 + (d&3) ] = Wh[d][col0+c]
    for (int idx = tid; idx < 512 * 16; idx += RNN_THREADS) {
        int d  = idx >> 4;
        int c4 = (idx & 15) << 2;
        int f  = d >> 2;
        int dl = d & 3;
        float4 v = *(const float4*)(Wh + (size_t)d * DIM + col0 + c4);
        float vv[4] = {v.x, v.y, v.z, v.w};
        #pragma unroll
        for (int q = 0; q < 4; q++) {
            int c = c4 + q;
            int p = (f + 2 * (c >> 3)) & 127;
            wt[c * CSTR + (p << 2) + dl] = vv[q];
        }
    }

    // thread mapping (R7)
    const int kq   = lane & 7;                 // K-slice 0..7 (64 d each)
    const int cqlo = lane >> 3;                // 0..3
    const int cq   = ((warp & 1) << 2) | cqlo; // 0..7  -> 8 cols each
    const int rq   = warp >> 1;                // 0..1  -> 8 rows each
    const int c0   = cq << 3;                  // col in [0,64)
    const int r0   = rq << 3;                  // row in [0,16)
    const int rot  = 2 * cq;                   // wt rotation for these cols

    const int outrow  = row0 + r0 + kq;        // this thread's output row
    const int outcolg = col0 + c0;             // global col base (8 cols)
    const int* xrow = x + (size_t)outrow * SEQL;

    __syncthreads();        // wt + barrier init complete (CTA)
    cluster_sync_all();     // peers' barriers initialized before any arrival

    unsigned ph0 = 0, ph1 = 0;   // per-thread parity trackers for bar0/bar1

    for (int l = 0; l < SEQL; l++) {
        // prefetch xin early (independent of sync / h)
        int token = __ldg(xrow + l);
        const float* embrow = g_embW + (size_t)token * DIM + outcolg;
        float4 xin0 = __ldg((const float4*)embrow);
        float4 xin1 = __ldg((const float4*)(embrow + 4));

        float fin[8];
        #pragma unroll
        for (int i = 0; i < 8; i++) fin[i] = 0.f;

        if (l > 0) {
            // ---- wait: all 8 cluster CTAs finished step l-1 ----
            int b = (l - 1) & 1;
            if (b == 0) { mbar_wait_cluster(bar0, ph0); ph0 ^= 1u; }
            else        { mbar_wait_cluster(bar1, ph1); ph1 ^= 1u; }

            // ---- stage 16x512 h block (32KB) from L2, coalesced ----
            const float* hsrc = g_h + (size_t)(l & 1) * (BATCH * DIM) + (size_t)row0 * DIM;
            #pragma unroll
            for (int k = 0; k < 16; k++) {
                int idx = tid + (k << 7);         // 0..2047 float4
                int row = idx >> 7;
                int cc4 = idx & 127;
                float4 v = __ldcg((const float4*)(hsrc + row * DIM) + cc4);
                *(float4*)(hs + row * CSTR + (cc4 << 2)) = v;
            }
            __syncthreads();

            // ---- h @ Wh: 8 rows x 8 cols x 64 K, fp32x2 packed over K ----
            ull acc[8][8];
            #pragma unroll
            for (int j = 0; j < 8; j++)
                #pragma unroll
                for (int i = 0; i < 8; i++) acc[j][i] = 0ull;

            const float* wbase = wt + c0 * CSTR;

            #pragma unroll 4
            for (int dq = 0; dq < 16; dq++) {
                int s   = (dq + kq) & 15;
                int di  = (kq << 4) + s;           // natural float4 index (hv)
                int dr  = (di + rot) & 127;        // rotated float4 index (wv)
                int dbh = di << 2;
                int dbw = dr << 2;

                ulonglong2 wv[8];
                #pragma unroll
                for (int i = 0; i < 8; i++)
                    wv[i] = *(const ulonglong2*)(wbase + i * CSTR + dbw);

                #pragma unroll
                for (int j = 0; j < 8; j++) {
                    ulonglong2 hv = *(const ulonglong2*)(hs + (r0 + j) * CSTR + dbh);
                    #pragma unroll
                    for (int i = 0; i < 8; i++) {
                        acc[j][i] = fma2(hv.x, wv[i].x, acc[j][i]);
                        acc[j][i] = fma2(hv.y, wv[i].y, acc[j][i]);
                    }
                }
            }

            // ---- reduce-scatter over 8 kq lanes (rounds xor 4,2,1) ----
            #pragma unroll
            for (int i = 0; i < 8; i++) {
                #pragma unroll
                for (int jj = 0; jj < 4; jj++) {
                    ull s = (kq & 4) ? acc[jj][i] : acc[jj + 4][i];
                    ull r = shflx64(s, 4);
                    ull kkeep = (kq & 4) ? acc[jj + 4][i] : acc[jj][i];
                    acc[jj][i] = add2(kkeep, r);
                }
                #pragma unroll
                for (int jj = 0; jj < 2; jj++) {
                    ull s = (kq & 2) ? acc[jj][i] : acc[jj + 2][i];
                    ull r = shflx64(s, 2);
                    ull kkeep = (kq & 2) ? acc[jj + 2][i] : acc[jj][i];
                    acc[jj][i] = add2(kkeep, r);
                }
                {
                    ull s = (kq & 1) ? acc[0][i] : acc[1][i];
                    ull r = shflx64(s, 1);
                    ull kkeep = (kq & 1) ? acc[1][i] : acc[0][i];
                    ull f = add2(kkeep, r);
                    float2 ff = *(float2*)&f;
                    fin[i] = ff.x + ff.y;    // horizontal add of the K pair streams
                }
            }
        }

        float4 hn0, hn1;
        hn0.x = tanhf(fin[0] + xin0.x);
        hn0.y = tanhf(fin[1] + xin0.y);
        hn0.z = tanhf(fin[2] + xin0.z);
        hn0.w = tanhf(fin[3] + xin0.w);
        hn1.x = tanhf(fin[4] + xin1.x);
        hn1.y = tanhf(fin[5] + xin1.y);
        hn1.z = tanhf(fin[6] + xin1.z);
        hn1.w = tanhf(fin[7] + xin1.w);

        float* hdst = g_h + (size_t)((l + 1) & 1) * (BATCH * DIM)
                          + (size_t)outrow * DIM + outcolg;
        __stcg((float4*)hdst,       hn0);
        __stcg((float4*)(hdst + 4), hn1);

        // ---- publish step l: CTA barrier, then arrive on all 8 cluster CTAs ----
        __syncthreads();    // all threads' h-stores ordered-before the arrivals
        if (tid < CLUSTER_CTAS && l < SEQL - 1) {
            unsigned bar = (l & 1) ? bar1 : bar0;
            mbar_arrive_cluster(bar, (unsigned)tid);
        }
    }

    cluster_sync_all();     // no in-flight arrivals can target a departed CTA
    if (tid == 0) { mbar_inval(bar0); mbar_inval(bar1); }
}

// ---------------- kernel 3: logits + softmax --------------------------------
__global__ __launch_bounds__(256) void softmax_kernel(
    const float* __restrict__ Wd,   // [512][20]
    const float* __restrict__ bd,   // [20]
    float* __restrict__ out)        // [256][20]
{
    int b    = blockIdx.x * 8 + (threadIdx.x >> 5);
    int lane = threadIdx.x & 31;
    if (b >= BATCH) return;

    const float* h = g_h + (size_t)b * DIM;

    float acc[NCLS];
    #pragma unroll
    for (int c = 0; c < NCLS; c++) acc[c] = 0.f;

    for (int d = lane; d < DIM; d += 32) {
        float hv = __ldcg(h + d);
        #pragma unroll
        for (int c = 0; c < NCLS; c++)
            acc[c] += hv * Wd[d * NCLS + c];
    }
    #pragma unroll
    for (int c = 0; c < NCLS; c++) {
        #pragma unroll
        for (int off = 16; off > 0; off >>= 1)
            acc[c] += __shfl_xor_sync(0xFFFFFFFFu, acc[c], off);
    }
    if (lane == 0) {
        float logit[NCLS];
        float m = -1e30f;
        #pragma unroll
        for (int c = 0; c < NCLS; c++) {
            logit[c] = acc[c] + bd[c];
            m = fmaxf(m, logit[c]);
        }
        float s = 0.f;
        #pragma unroll
        for (int c = 0; c < NCLS; c++) {
            logit[c] = expf(logit[c] - m);
            s += logit[c];
        }
        float inv = 1.0f / s;
        #pragma unroll
        for (int c = 0; c < NCLS; c++)
            out[b * NCLS + c] = logit[c] * inv;
    }
}

// ---------------- launch ----------------------------------------------------
extern "C" void kernel_launch(void* const* d_in, const int* in_sizes, int n_in,
                              void* d_out, int out_size)
{
    const int*   x   = (const int*)  d_in[0];
    const float* emb = (const float*)d_in[1];
    const float* Wx  = (const float*)d_in[2];
    const float* Wh  = (const float*)d_in[3];
    const float* b   = (const float*)d_in[4];
    const float* Wd  = (const float*)d_in[5];
    const float* bd  = (const float*)d_in[6];
    float* out = (float*)d_out;

    // 1) embW = emb @ Wx + b
    embw_gemm<<<dim3(DIM / 128, (VOCAB + 127) / 128), 256>>>(emb, Wx, b, VOCAB);

    // 2) persistent recurrence: 16 clusters x 8 CTAs x 128 threads, ~165KB smem
    cudaFuncSetAttribute(rnn_recur, cudaFuncAttributeMaxDynamicSharedMemorySize,
                         RNN_SMEM_BYTES);
    rnn_recur<<<128, RNN_THREADS, RNN_SMEM_BYTES>>>(x, Wh);

    // 3) logits + softmax
    softmax_kernel<<<(BATCH + 7) / 8, 256>>>(Wd, bd, out);
}

// round 11
// speedup vs baseline: 1.5988x; 1.5988x over previous
#include <cuda_runtime.h>
#include <cuda_bf16.h>
#include <math.h>

// Problem constants
#define VOCAB 50000
#define DIM   512
#define SEQL  512
#define BATCH 256
#define NCLS  20

// smem layout (floats): wt[64][516] rotated+transposed Wh slice, hs[16][516]
#define CSTR  516
#define RNN_SMEM_FLOATS ((64 + 16) * CSTR)
#define RNN_SMEM_BYTES  (RNN_SMEM_FLOATS * 4)   // 165,120 B
#define RNN_THREADS 128

typedef unsigned long long ull;

// ---------------- device scratch (no runtime alloc allowed) ----------------
__device__ float g_embW[(size_t)VOCAB * DIM];       // emb @ Wx + b, ~100 MB
__device__ float g_h[2 * BATCH * DIM];              // ping-pong hidden state
__device__ unsigned g_flags[16][32];                // per-CTA step flags (8 used/group)

// strong acquire/release flag ops (R7-proven protocol)
__device__ __forceinline__ unsigned ldflag_acq(const unsigned* p) {
    unsigned v;
    asm volatile("ld.acquire.gpu.global.u32 %0, [%1];" : "=r"(v) : "l"(p) : "memory");
    return v;
}
__device__ __forceinline__ void stflag_rel(unsigned* p, unsigned v) {
    asm volatile("st.release.gpu.global.u32 [%0], %1;" :: "l"(p), "r"(v) : "memory");
}

// packed fp32x2 math (sm_103a native; ptxas never auto-generates these)
__device__ __forceinline__ ull fma2(ull a, ull b, ull c) {
    ull d;
    asm("fma.rn.f32x2 %0, %1, %2, %3;" : "=l"(d) : "l"(a), "l"(b), "l"(c));
    return d;
}
__device__ __forceinline__ ull add2(ull a, ull b) {
    ull d;
    asm("add.rn.f32x2 %0, %1, %2;" : "=l"(d) : "l"(a), "l"(b));
    return d;
}
__device__ __forceinline__ ull shflx64(ull v, int m) {
    unsigned lo = (unsigned)v, hi = (unsigned)(v >> 32);
    lo = __shfl_xor_sync(0xffffffffu, lo, m);
    hi = __shfl_xor_sync(0xffffffffu, hi, m);
    return ((ull)hi << 32) | (ull)lo;
}

// ---------------- kernel 1: embW = emb @ Wx + b  (fp32 tiled GEMM) ----------
// BM=128, BN=128, BK=16, 256 threads, 8x8 per thread (measured 519us).
__global__ __launch_bounds__(256) void embw_gemm(
    const float* __restrict__ A,    // emb [M][512]
    const float* __restrict__ B,    // Wx  [512][512]
    const float* __restrict__ bias, // b [512]
    int M)
{
    __shared__ float As[16][132];   // transposed A tile [k][m], padded
    __shared__ float Bs[16][128];   // [k][n]

    const int tid  = threadIdx.x;
    const int row0 = blockIdx.y * 128;
    const int col0 = blockIdx.x * 128;
    const int tm = tid >> 4;        // 0..15 -> 8 rows each
    const int tn = tid & 15;        // 0..15 -> cols tn*4 and 64+tn*4

    float4 acc0[8], acc1[8];
    #pragma unroll
    for (int i = 0; i < 8; i++) {
        acc0[i] = make_float4(0.f, 0.f, 0.f, 0.f);
        acc1[i] = make_float4(0.f, 0.f, 0.f, 0.f);
    }

    for (int k0 = 0; k0 < DIM; k0 += 16) {
        #pragma unroll
        for (int t = 0; t < 2; t++) {
            int idx = tid + t * 256;
            int am  = idx >> 2;
            int ak4 = (idx & 3) << 2;
            float4 av = make_float4(0.f, 0.f, 0.f, 0.f);
            if (row0 + am < M)
                av = *(const float4*)(A + (size_t)(row0 + am) * DIM + k0 + ak4);
            As[ak4 + 0][am] = av.x;
            As[ak4 + 1][am] = av.y;
            As[ak4 + 2][am] = av.z;
            As[ak4 + 3][am] = av.w;
        }
        #pragma unroll
        for (int t = 0; t < 2; t++) {
            int idx = tid + t * 256;
            int bk  = idx >> 5;
            int bn4 = (idx & 31) << 2;
            *(float4*)&Bs[bk][bn4] =
                *(const float4*)(B + (size_t)(k0 + bk) * DIM + col0 + bn4);
        }
        __syncthreads();

        #pragma unroll
        for (int kk = 0; kk < 16; kk++) {
            float4 b0 = *(const float4*)&Bs[kk][tn << 2];
            float4 b1 = *(const float4*)&Bs[kk][64 + (tn << 2)];
            float4 a0 = *(const float4*)&As[kk][tm * 8];
            float4 a1 = *(const float4*)&As[kk][tm * 8 + 4];
            float av[8] = {a0.x, a0.y, a0.z, a0.w, a1.x, a1.y, a1.z, a1.w};
            #pragma unroll
            for (int i = 0; i < 8; i++) {
                acc0[i].x += av[i] * b0.x; acc0[i].y += av[i] * b0.y;
                acc0[i].z += av[i] * b0.z; acc0[i].w += av[i] * b0.w;
                acc1[i].x += av[i] * b1.x; acc1[i].y += av[i] * b1.y;
                acc1[i].z += av[i] * b1.z; acc1[i].w += av[i] * b1.w;
            }
        }
        __syncthreads();
    }

    float4 bb0 = *(const float4*)(bias + col0 + (tn << 2));
    float4 bb1 = *(const float4*)(bias + col0 + 64 + (tn << 2));
    #pragma unroll
    for (int i = 0; i < 8; i++) {
        int row = row0 + tm * 8 + i;
        if (row < M) {
            float4 o0, o1;
            o0.x = acc0[i].x + bb0.x; o0.y = acc0[i].y + bb0.y;
            o0.z = acc0[i].z + bb0.z; o0.w = acc0[i].w + bb0.w;
            o1.x = acc1[i].x + bb1.x; o1.y = acc1[i].y + bb1.y;
            o1.z = acc1[i].z + bb1.z; o1.w = acc1[i].w + bb1.w;
            *(float4*)(g_embW + (size_t)row * DIM + col0 + (tn << 2))      = o0;
            *(float4*)(g_embW + (size_t)row * DIM + col0 + 64 + (tn << 2)) = o1;
        }
    }
}

// ---------------- kernel 2: persistent RNN recurrence -----------------------
// R7 engine (best measured).  128 CTAs: blockIdx = rg*8 + cg.
// rg in [0,16): 16 batch rows.  cg in [0,8): 64 cols.  128 threads/CTA.
// Thread tile: 8 rows x 8 cols x 64 K (kq in [0,8) splits K).
// Fence-free publish: bar.sync (CTA-scope fence) -> tid0 st.release.gpu;
// consume: ld.acquire.gpu by 8 lanes -> __syncwarp() ordering bridge.
__global__ __launch_bounds__(RNN_THREADS, 1) void rnn_recur(
    const int*   __restrict__ x,    // [256][512] tokens
    const float* __restrict__ Wh)   // [512][512]
{
    extern __shared__ float smem[];
    float* wt = smem;                 // [64][CSTR] rotated transpose
    float* hs = smem + 64 * CSTR;     // [16][CSTR] linear

    const int tid  = threadIdx.x;
    const int warp = tid >> 5;
    const int lane = tid & 31;
    const int rg   = blockIdx.x >> 3;
    const int cg   = blockIdx.x & 7;
    const int col0 = cg * 64;
    const int row0 = rg * 16;

    // one-time rotated transposed load:
    // wt[c][ ((d>>2 + 2*(c>>3)) & 127)*4 + (d&3) ] = Wh[d][col0+c]
    for (int idx = tid; idx < 512 * 16; idx += RNN_THREADS) {
        int d  = idx >> 4;
        int c4 = (idx & 15) << 2;
        int f  = d >> 2;
        int dl = d & 3;
        float4 v = *(const float4*)(Wh + (size_t)d * DIM + col0 + c4);
        float vv[4] = {v.x, v.y, v.z, v.w};
        #pragma unroll
        for (int q = 0; q < 4; q++) {
            int c = c4 + q;
            int p = (f + 2 * (c >> 3)) & 127;
            wt[c * CSTR + (p << 2) + dl] = vv[q];
        }
    }

    // thread mapping (R7)
    const int kq   = lane & 7;                 // K-slice 0..7 (64 d each)
    const int cqlo = lane >> 3;                // 0..3
    const int cq   = ((warp & 1) << 2) | cqlo; // 0..7  -> 8 cols each
    const int rq   = warp >> 1;                // 0..1  -> 8 rows each
    const int c0   = cq << 3;                  // col in [0,64)
    const int r0   = rq << 3;                  // row in [0,16)
    const int rot  = 2 * cq;                   // wt rotation for these cols

    const int outrow  = row0 + r0 + kq;        // this thread's output row
    const int outcolg = col0 + c0;             // global col base (8 cols)
    const int* xrow = x + (size_t)outrow * SEQL;

    unsigned* myflag = &g_flags[rg][cg];
    const unsigned base = ldflag_acq(myflag);  // replay-safe monotonic base

    __syncthreads();

    for (int l = 0; l < SEQL; l++) {
        // prefetch xin early (independent of sync / h)
        int token = __ldg(xrow + l);
        const float* embrow = g_embW + (size_t)token * DIM + outcolg;
        float4 xin0 = __ldg((const float4*)embrow);
        float4 xin1 = __ldg((const float4*)(embrow + 4));

        float fin[8];
        #pragma unroll
        for (int i = 0; i < 8; i++) fin[i] = 0.f;

        if (l > 0) {
            // ---- per-group acquire wait (8 producers) ----
            unsigned target = base + (unsigned)l;
            if (lane < 8) {
                const unsigned* f = &g_flags[rg][lane];
                while ((int)(ldflag_acq(f) - target) < 0) { }
            }
            __syncwarp();   // ordering bridge to non-polling lanes

            // ---- stage 16x512 h block (32KB) from L2, coalesced ----
            const float* hsrc = g_h + (size_t)(l & 1) * (BATCH * DIM) + (size_t)row0 * DIM;
            #pragma unroll
            for (int k = 0; k < 16; k++) {
                int idx = tid + (k << 7);         // 0..2047 float4
                int row = idx >> 7;
                int cc4 = idx & 127;
                float4 v = __ldcg((const float4*)(hsrc + row * DIM) + cc4);
                *(float4*)(hs + row * CSTR + (cc4 << 2)) = v;
            }
            __syncthreads();

            // ---- h @ Wh: 8 rows x 8 cols x 64 K, fp32x2 packed over K ----
            ull acc[8][8];
            #pragma unroll
            for (int j = 0; j < 8; j++)
                #pragma unroll
                for (int i = 0; i < 8; i++) acc[j][i] = 0ull;

            const float* wbase = wt + c0 * CSTR;

            #pragma unroll 4
            for (int dq = 0; dq < 16; dq++) {
                int s   = (dq + kq) & 15;
                int di  = (kq << 4) + s;           // natural float4 index (hv)
                int dr  = (di + rot) & 127;        // rotated float4 index (wv)
                int dbh = di << 2;
                int dbw = dr << 2;

                ulonglong2 wv[8];
                #pragma unroll
                for (int i = 0; i < 8; i++)
                    wv[i] = *(const ulonglong2*)(wbase + i * CSTR + dbw);

                #pragma unroll
                for (int j = 0; j < 8; j++) {
                    ulonglong2 hv = *(const ulonglong2*)(hs + (r0 + j) * CSTR + dbh);
                    #pragma unroll
                    for (int i = 0; i < 8; i++) {
                        acc[j][i] = fma2(hv.x, wv[i].x, acc[j][i]);
                        acc[j][i] = fma2(hv.y, wv[i].y, acc[j][i]);
                    }
                }
            }

            // ---- reduce-scatter over 8 kq lanes (rounds xor 4,2,1) ----
            #pragma unroll
            for (int i = 0; i < 8; i++) {
                #pragma unroll
                for (int jj = 0; jj < 4; jj++) {
                    ull s = (kq & 4) ? acc[jj][i] : acc[jj + 4][i];
                    ull r = shflx64(s, 4);
                    ull kkeep = (kq & 4) ? acc[jj + 4][i] : acc[jj][i];
                    acc[jj][i] = add2(kkeep, r);
                }
                #pragma unroll
                for (int jj = 0; jj < 2; jj++) {
                    ull s = (kq & 2) ? acc[jj][i] : acc[jj + 2][i];
                    ull r = shflx64(s, 2);
                    ull kkeep = (kq & 2) ? acc[jj + 2][i] : acc[jj][i];
                    acc[jj][i] = add2(kkeep, r);
                }
                {
                    ull s = (kq & 1) ? acc[0][i] : acc[1][i];
                    ull r = shflx64(s, 1);
                    ull kkeep = (kq & 1) ? acc[1][i] : acc[0][i];
                    ull f = add2(kkeep, r);
                    float2 ff = *(float2*)&f;
                    fin[i] = ff.x + ff.y;    // horizontal add of the K pair streams
                }
            }
        }

        float4 hn0, hn1;
        hn0.x = tanhf(fin[0] + xin0.x);
        hn0.y = tanhf(fin[1] + xin0.y);
        hn0.z = tanhf(fin[2] + xin0.z);
        hn0.w = tanhf(fin[3] + xin0.w);
        hn1.x = tanhf(fin[4] + xin1.x);
        hn1.y = tanhf(fin[5] + xin1.y);
        hn1.z = tanhf(fin[6] + xin1.z);
        hn1.w = tanhf(fin[7] + xin1.w);

        float* hdst = g_h + (size_t)((l + 1) & 1) * (BATCH * DIM)
                          + (size_t)outrow * DIM + outcolg;
        __stcg((float4*)hdst,       hn0);
        __stcg((float4*)(hdst + 4), hn1);

        // ---- publish: CTA barrier (cta-scope fence) then release store ----
        __syncthreads();
        if (tid == 0) stflag_rel(myflag, base + (unsigned)(l + 1));
    }
    // flags end at base+512: next launch re-reads as its new base (no reset)
}

// ---------------- kernel 3: logits + softmax --------------------------------
__global__ __launch_bounds__(256) void softmax_kernel(
    const float* __restrict__ Wd,   // [512][20]
    const float* __restrict__ bd,   // [20]
    float* __restrict__ out)        // [256][20]
{
    int b    = blockIdx.x * 8 + (threadIdx.x >> 5);
    int lane = threadIdx.x & 31;
    if (b >= BATCH) return;

    const float* h = g_h + (size_t)b * DIM;

    float acc[NCLS];
    #pragma unroll
    for (int c = 0; c < NCLS; c++) acc[c] = 0.f;

    for (int d = lane; d < DIM; d += 32) {
        float hv = __ldcg(h + d);
        #pragma unroll
        for (int c = 0; c < NCLS; c++)
            acc[c] += hv * Wd[d * NCLS + c];
    }
    #pragma unroll
    for (int c = 0; c < NCLS; c++) {
        #pragma unroll
        for (int off = 16; off > 0; off >>= 1)
            acc[c] += __shfl_xor_sync(0xFFFFFFFFu, acc[c], off);
    }
    if (lane == 0) {
        float logit[NCLS];
        float m = -1e30f;
        #pragma unroll
        for (int c = 0; c < NCLS; c++) {
            logit[c] = acc[c] + bd[c];
            m = fmaxf(m, logit[c]);
        }
        float s = 0.f;
        #pragma unroll
        for (int c = 0; c < NCLS; c++) {
            logit[c] = expf(logit[c] - m);
            s += logit[c];
        }
        float inv = 1.0f / s;
        #pragma unroll
        for (int c = 0; c < NCLS; c++)
            out[b * NCLS + c] = logit[c] * inv;
    }
}

// ---------------- launch ----------------------------------------------------
extern "C" void kernel_launch(void* const* d_in, const int* in_sizes, int n_in,
                              void* d_out, int out_size)
{
    const int*   x   = (const int*)  d_in[0];
    const float* emb = (const float*)d_in[1];
    const float* Wx  = (const float*)d_in[2];
    const float* Wh  = (const float*)d_in[3];
    const float* b   = (const float*)d_in[4];
    const float* Wd  = (const float*)d_in[5];
    const float* bd  = (const float*)d_in[6];
    float* out = (float*)d_out;

    // 1) embW = emb @ Wx + b
    embw_gemm<<<dim3(DIM / 128, (VOCAB + 127) / 128), 256>>>(emb, Wx, b, VOCAB);

    // 2) persistent recurrence (128 CTAs x 128 threads, ~165KB smem, all resident)
    cudaFuncSetAttribute(rnn_recur, cudaFuncAttributeMaxDynamicSharedMemorySize,
                         RNN_SMEM_BYTES);
    rnn_recur<<<128, RNN_THREADS, RNN_SMEM_BYTES>>>(x, Wh);

    // 3) logits + softmax
    softmax_kernel<<<(BATCH + 7) / 8, 256>>>(Wd, bd, out);
}

// round 12
// speedup vs baseline: 1.6080x; 1.0058x over previous
#include <cuda_runtime.h>
#include <cuda_bf16.h>
#include <math.h>

// Problem constants
#define VOCAB 50000
#define DIM   512
#define SEQL  512
#define BATCH 256
#define NCLS  20

// smem layout (floats): wt[64][516] rotated+transposed Wh slice, hs[16][516]
#define CSTR  516
#define RNN_SMEM_FLOATS ((64 + 16) * CSTR)
#define RNN_SMEM_BYTES  (RNN_SMEM_FLOATS * 4)   // 165,120 B
#define RNN_THREADS 128

typedef unsigned long long ull;

// ---------------- device scratch (no runtime alloc allowed) ----------------
__device__ float g_embW[(size_t)VOCAB * DIM];       // emb @ Wx + b, ~100 MB
__device__ float g_h[2 * BATCH * DIM];              // ping-pong hidden state
__device__ unsigned g_flags[16][32];                // per-CTA step flags (8 used/group)

// strong acquire/release flag ops (R7/R11-proven protocol)
__device__ __forceinline__ unsigned ldflag_acq(const unsigned* p) {
    unsigned v;
    asm volatile("ld.acquire.gpu.global.u32 %0, [%1];" : "=r"(v) : "l"(p) : "memory");
    return v;
}
__device__ __forceinline__ void stflag_rel(unsigned* p, unsigned v) {
    asm volatile("st.release.gpu.global.u32 [%0], %1;" :: "l"(p), "r"(v) : "memory");
}

// hardware tanh (MUFU.TANH): max err ~2^-11 abs; recurrence is contractive
// (measured fp32 chain: per-step 1e-6 -> final 3e-7), expected final ~1e-4.
__device__ __forceinline__ float tanhfast(float x) {
    float y;
    asm("tanh.approx.f32 %0, %1;" : "=f"(y) : "f"(x));
    return y;
}

// packed fp32x2 math (sm_103a native; ptxas never auto-generates these)
__device__ __forceinline__ ull fma2(ull a, ull b, ull c) {
    ull d;
    asm("fma.rn.f32x2 %0, %1, %2, %3;" : "=l"(d) : "l"(a), "l"(b), "l"(c));
    return d;
}
__device__ __forceinline__ ull add2(ull a, ull b) {
    ull d;
    asm("add.rn.f32x2 %0, %1, %2;" : "=l"(d) : "l"(a), "l"(b));
    return d;
}
__device__ __forceinline__ ull shflx64(ull v, int m) {
    unsigned lo = (unsigned)v, hi = (unsigned)(v >> 32);
    lo = __shfl_xor_sync(0xffffffffu, lo, m);
    hi = __shfl_xor_sync(0xffffffffu, hi, m);
    return ((ull)hi << 32) | (ull)lo;
}

// ---------------- kernel 1: embW = emb @ Wx + b  (fp32 tiled GEMM) ----------
// BM=128, BN=128, BK=16, 256 threads, 8x8 per thread; 2 CTAs/SM target.
__global__ __launch_bounds__(256, 2) void embw_gemm(
    const float* __restrict__ A,    // emb [M][512]
    const float* __restrict__ B,    // Wx  [512][512]
    const float* __restrict__ bias, // b [512]
    int M)
{
    __shared__ float As[16][132];   // transposed A tile [k][m], padded
    __shared__ float Bs[16][128];   // [k][n]

    const int tid  = threadIdx.x;
    const int row0 = blockIdx.y * 128;
    const int col0 = blockIdx.x * 128;
    const int tm = tid >> 4;        // 0..15 -> 8 rows each
    const int tn = tid & 15;        // 0..15 -> cols tn*4 and 64+tn*4

    float4 acc0[8], acc1[8];
    #pragma unroll
    for (int i = 0; i < 8; i++) {
        acc0[i] = make_float4(0.f, 0.f, 0.f, 0.f);
        acc1[i] = make_float4(0.f, 0.f, 0.f, 0.f);
    }

    for (int k0 = 0; k0 < DIM; k0 += 16) {
        #pragma unroll
        for (int t = 0; t < 2; t++) {
            int idx = tid + t * 256;
            int am  = idx >> 2;
            int ak4 = (idx & 3) << 2;
            float4 av = make_float4(0.f, 0.f, 0.f, 0.f);
            if (row0 + am < M)
                av = *(const float4*)(A + (size_t)(row0 + am) * DIM + k0 + ak4);
            As[ak4 + 0][am] = av.x;
            As[ak4 + 1][am] = av.y;
            As[ak4 + 2][am] = av.z;
            As[ak4 + 3][am] = av.w;
        }
        #pragma unroll
        for (int t = 0; t < 2; t++) {
            int idx = tid + t * 256;
            int bk  = idx >> 5;
            int bn4 = (idx & 31) << 2;
            *(float4*)&Bs[bk][bn4] =
                *(const float4*)(B + (size_t)(k0 + bk) * DIM + col0 + bn4);
        }
        __syncthreads();

        #pragma unroll
        for (int kk = 0; kk < 16; kk++) {
            float4 b0 = *(const float4*)&Bs[kk][tn << 2];
            float4 b1 = *(const float4*)&Bs[kk][64 + (tn << 2)];
            float4 a0 = *(const float4*)&As[kk][tm * 8];
            float4 a1 = *(const float4*)&As[kk][tm * 8 + 4];
            float av[8] = {a0.x, a0.y, a0.z, a0.w, a1.x, a1.y, a1.z, a1.w};
            #pragma unroll
            for (int i = 0; i < 8; i++) {
                acc0[i].x += av[i] * b0.x; acc0[i].y += av[i] * b0.y;
                acc0[i].z += av[i] * b0.z; acc0[i].w += av[i] * b0.w;
                acc1[i].x += av[i] * b1.x; acc1[i].y += av[i] * b1.y;
                acc1[i].z += av[i] * b1.z; acc1[i].w += av[i] * b1.w;
            }
        }
        __syncthreads();
    }

    float4 bb0 = *(const float4*)(bias + col0 + (tn << 2));
    float4 bb1 = *(const float4*)(bias + col0 + 64 + (tn << 2));
    #pragma unroll
    for (int i = 0; i < 8; i++) {
        int row = row0 + tm * 8 + i;
        if (row < M) {
            float4 o0, o1;
            o0.x = acc0[i].x + bb0.x; o0.y = acc0[i].y + bb0.y;
            o0.z = acc0[i].z + bb0.z; o0.w = acc0[i].w + bb0.w;
            o1.x = acc1[i].x + bb1.x; o1.y = acc1[i].y + bb1.y;
            o1.z = acc1[i].z + bb1.z; o1.w = acc1[i].w + bb1.w;
            *(float4*)(g_embW + (size_t)row * DIM + col0 + (tn << 2))      = o0;
            *(float4*)(g_embW + (size_t)row * DIM + col0 + 64 + (tn << 2)) = o1;
        }
    }
}

// ---------------- kernel 2: persistent RNN recurrence -----------------------
// R11 engine.  128 CTAs: blockIdx = rg*8 + cg.  128 threads/CTA.
// Thread tile: 8 rows x 8 cols x 64 K (kq in [0,8) splits K).
// New in R12: hardware tanh; own 16x64 h-block written directly to smem after
// the publish barrier (staging skips own chunk -> less L2 traffic + latency).
__global__ __launch_bounds__(RNN_THREADS, 1) void rnn_recur(
    const int*   __restrict__ x,    // [256][512] tokens
    const float* __restrict__ Wh)   // [512][512]
{
    extern __shared__ float smem[];
    float* wt = smem;                 // [64][CSTR] rotated transpose
    float* hs = smem + 64 * CSTR;     // [16][CSTR] linear, cols = global d

    const int tid  = threadIdx.x;
    const int warp = tid >> 5;
    const int lane = tid & 31;
    const int rg   = blockIdx.x >> 3;
    const int cg   = blockIdx.x & 7;
    const int col0 = cg * 64;
    const int row0 = rg * 16;

    // one-time rotated transposed load:
    // wt[c][ ((d>>2 + 2*(c>>3)) & 127)*4 + (d&3) ] = Wh[d][col0+c]
    for (int idx = tid; idx < 512 * 16; idx += RNN_THREADS) {
        int d  = idx >> 4;
        int c4 = (idx & 15) << 2;
        int f  = d >> 2;
        int dl = d & 3;
        float4 v = *(const float4*)(Wh + (size_t)d * DIM + col0 + c4);
        float vv[4] = {v.x, v.y, v.z, v.w};
        #pragma unroll
        for (int q = 0; q < 4; q++) {
            int c = c4 + q;
            int p = (f + 2 * (c >> 3)) & 127;
            wt[c * CSTR + (p << 2) + dl] = vv[q];
        }
    }

    // thread mapping (R7/R11)
    const int kq   = lane & 7;                 // K-slice 0..7 (64 d each)
    const int cqlo = lane >> 3;                // 0..3
    const int cq   = ((warp & 1) << 2) | cqlo; // 0..7  -> 8 cols each
    const int rq   = warp >> 1;                // 0..1  -> 8 rows each
    const int c0   = cq << 3;                  // col in [0,64)
    const int r0   = rq << 3;                  // row in [0,16)
    const int rot  = 2 * cq;                   // wt rotation for these cols

    const int outrow  = row0 + r0 + kq;        // this thread's output row
    const int outrloc = r0 + kq;               // local row in hs
    const int outcolg = col0 + c0;             // global col base (8 cols)
    const int* xrow = x + (size_t)outrow * SEQL;

    // staging role: thread stages column-float4 index == tid, 16 rows deep.
    // threads whose column falls in this CTA's own 64-col chunk skip staging.
    const bool stager = ((tid >> 4) != cg);

    unsigned* myflag = &g_flags[rg][cg];
    const unsigned base = ldflag_acq(myflag);  // replay-safe monotonic base

    __syncthreads();

    for (int l = 0; l < SEQL; l++) {
        // prefetch xin early (independent of sync / h)
        int token = __ldg(xrow + l);
        const float* embrow = g_embW + (size_t)token * DIM + outcolg;
        float4 xin0 = __ldg((const float4*)embrow);
        float4 xin1 = __ldg((const float4*)(embrow + 4));

        float fin[8];
        #pragma unroll
        for (int i = 0; i < 8; i++) fin[i] = 0.f;

        if (l > 0) {
            // ---- per-group acquire wait (7 remote producers; own chunk local) ----
            unsigned target = base + (unsigned)l;
            if (lane < 8 && lane != cg) {
                const unsigned* f = &g_flags[rg][lane];
                while ((int)(ldflag_acq(f) - target) < 0) { }
            }
            __syncwarp();   // ordering bridge to non-polling lanes

            // ---- stage 16x448 sibling h data (28KB) from L2, deep MLP ----
            if (stager) {
                const float4* src = (const float4*)(g_h
                    + (size_t)(l & 1) * (BATCH * DIM) + (size_t)row0 * DIM) + tid;
                float4* dst = (float4*)(hs) + tid;
                #pragma unroll
                for (int k = 0; k < 16; k++)
                    dst[k * (CSTR / 4)] = __ldcg(src + k * (DIM / 4));
            }
            __syncthreads();

            // ---- h @ Wh: 8 rows x 8 cols x 64 K, fp32x2 packed over K ----
            ull acc[8][8];
            #pragma unroll
            for (int j = 0; j < 8; j++)
                #pragma unroll
                for (int i = 0; i < 8; i++) acc[j][i] = 0ull;

            const float* wbase = wt + c0 * CSTR;

            #pragma unroll 4
            for (int dq = 0; dq < 16; dq++) {
                int s   = (dq + kq) & 15;
                int di  = (kq << 4) + s;           // natural float4 index (hv)
                int dr  = (di + rot) & 127;        // rotated float4 index (wv)
                int dbh = di << 2;
                int dbw = dr << 2;

                ulonglong2 wv[8];
                #pragma unroll
                for (int i = 0; i < 8; i++)
                    wv[i] = *(const ulonglong2*)(wbase + i * CSTR + dbw);

                #pragma unroll
                for (int j = 0; j < 8; j++) {
                    ulonglong2 hv = *(const ulonglong2*)(hs + (r0 + j) * CSTR + dbh);
                    #pragma unroll
                    for (int i = 0; i < 8; i++) {
                        acc[j][i] = fma2(hv.x, wv[i].x, acc[j][i]);
                        acc[j][i] = fma2(hv.y, wv[i].y, acc[j][i]);
                    }
                }
            }

            // ---- reduce-scatter over 8 kq lanes (rounds xor 4,2,1) ----
            #pragma unroll
            for (int i = 0; i < 8; i++) {
                #pragma unroll
                for (int jj = 0; jj < 4; jj++) {
                    ull s = (kq & 4) ? acc[jj][i] : acc[jj + 4][i];
                    ull r = shflx64(s, 4);
                    ull kkeep = (kq & 4) ? acc[jj + 4][i] : acc[jj][i];
                    acc[jj][i] = add2(kkeep, r);
                }
                #pragma unroll
                for (int jj = 0; jj < 2; jj++) {
                    ull s = (kq & 2) ? acc[jj][i] : acc[jj + 2][i];
                    ull r = shflx64(s, 2);
                    ull kkeep = (kq & 2) ? acc[jj + 2][i] : acc[jj][i];
                    acc[jj][i] = add2(kkeep, r);
                }
                {
                    ull s = (kq & 1) ? acc[0][i] : acc[1][i];
                    ull r = shflx64(s, 1);
                    ull kkeep = (kq & 1) ? acc[1][i] : acc[0][i];
                    ull f = add2(kkeep, r);
                    float2 ff = *(float2*)&f;
                    fin[i] = ff.x + ff.y;    // horizontal add of the K pair streams
                }
            }
        }

        float4 hn0, hn1;
        hn0.x = tanhfast(fin[0] + xin0.x);
        hn0.y = tanhfast(fin[1] + xin0.y);
        hn0.z = tanhfast(fin[2] + xin0.z);
        hn0.w = tanhfast(fin[3] + xin0.w);
        hn1.x = tanhfast(fin[4] + xin1.x);
        hn1.y = tanhfast(fin[5] + xin1.y);
        hn1.z = tanhfast(fin[6] + xin1.z);
        hn1.w = tanhfast(fin[7] + xin1.w);

        float* hdst = g_h + (size_t)((l + 1) & 1) * (BATCH * DIM)
                          + (size_t)outrow * DIM + outcolg;
        __stcg((float4*)hdst,       hn0);
        __stcg((float4*)(hdst + 4), hn1);

        // ---- publish: CTA barrier (cta-scope fence) then release store ----
        __syncthreads();
        if (tid == 0) stflag_rel(myflag, base + (unsigned)(l + 1));

        // own 16x64 block into hs for next step (race-free: next staging
        // __syncthreads orders these writes before any cross-thread read;
        // staging never touches this CTA's own column range)
        *(float4*)&hs[outrloc * CSTR + outcolg]     = hn0;
        *(float4*)&hs[outrloc * CSTR + outcolg + 4] = hn1;
    }
    // flags end at base+512: next launch re-reads as its new base (no reset)
}

// ---------------- kernel 3: logits + softmax --------------------------------
__global__ __launch_bounds__(256) void softmax_kernel(
    const float* __restrict__ Wd,   // [512][20]
    const float* __restrict__ bd,   // [20]
    float* __restrict__ out)        // [256][20]
{
    int b    = blockIdx.x * 8 + (threadIdx.x >> 5);
    int lane = threadIdx.x & 31;
    if (b >= BATCH) return;

    const float* h = g_h + (size_t)b * DIM;

    float acc[NCLS];
    #pragma unroll
    for (int c = 0; c < NCLS; c++) acc[c] = 0.f;

    for (int d = lane; d < DIM; d += 32) {
        float hv = __ldcg(h + d);
        #pragma unroll
        for (int c = 0; c < NCLS; c++)
            acc[c] += hv * Wd[d * NCLS + c];
    }
    #pragma unroll
    for (int c = 0; c < NCLS; c++) {
        #pragma unroll
        for (int off = 16; off > 0; off >>= 1)
            acc[c] += __shfl_xor_sync(0xFFFFFFFFu, acc[c], off);
    }
    if (lane == 0) {
        float logit[NCLS];
        float m = -1e30f;
        #pragma unroll
        for (int c = 0; c < NCLS; c++) {
            logit[c] = acc[c] + bd[c];
            m = fmaxf(m, logit[c]);
        }
        float s = 0.f;
        #pragma unroll
        for (int c = 0; c < NCLS; c++) {
            logit[c] = expf(logit[c] - m);
            s += logit[c];
        }
        float inv = 1.0f / s;
        #pragma unroll
        for (int c = 0; c < NCLS; c++)
            out[b * NCLS + c] = logit[c] * inv;
    }
}

// ---------------- launch ----------------------------------------------------
extern "C" void kernel_launch(void* const* d_in, const int* in_sizes, int n_in,
                              void* d_out, int out_size)
{
    const int*   x   = (const int*)  d_in[0];
    const float* emb = (const float*)d_in[1];
    const float* Wx  = (const float*)d_in[2];
    const float* Wh  = (const float*)d_in[3];
    const float* b   = (const float*)d_in[4];
    const float* Wd  = (const float*)d_in[5];
    const float* bd  = (const float*)d_in[6];
    float* out = (float*)d_out;

    // 1) embW = emb @ Wx + b
    embw_gemm<<<dim3(DIM / 128, (VOCAB + 127) / 128), 256>>>(emb, Wx, b, VOCAB);

    // 2) persistent recurrence (128 CTAs x 128 threads, ~165KB smem, all resident)
    cudaFuncSetAttribute(rnn_recur, cudaFuncAttributeMaxDynamicSharedMemorySize,
                         RNN_SMEM_BYTES);
    rnn_recur<<<128, RNN_THREADS, RNN_SMEM_BYTES>>>(x, Wh);

    // 3) logits + softmax
    softmax_kernel<<<(BATCH + 7) / 8, 256>>>(Wd, bd, out);
}